// round 3
// baseline (speedup 1.0000x reference)
#include <cuda_runtime.h>

// Problem constants
#define MM   1024
#define NN   2048
#define DVV  3
#define DCC  6
#define DD   8
#define BB   128
#define TT   5
#define CINC 48        // DC*D
#define CINP 52        // padded W1T row stride (floats, 16B-mult)
#define VINV 25        // DV*D + 1
#define VINP 28        // padded var width
#define HCC  192
#define HCH  96        // chk hidden half
#define HVV  100

#define PARTSZ ((size_t)MM * DCC * BB * DD)

typedef unsigned long long ull;

// Message buffers (edge-major: [edge][batch][D])
__device__ float g_cbuf[2 * PARTSZ];                  // check->var partial halves
__device__ float g_vbuf[(size_t)NN * DVV * BB * DD];  // var->check

// Pre-transposed / padded weights (filled by prologue kernels each replay)
__device__ float g_cw1t[(size_t)MM * HCC * CINP];     // [M][H][CINP]
__device__ float g_vw1t[(size_t)NN * HVV * VINP];     // [N][H][VINP]
__device__ float g_vw2p[(size_t)NN * HVV * VINP];     // [N][H][VINP]

__device__ __forceinline__ ull ffma2(ull a, ull b, ull c) {
    ull d; asm("fma.rn.f32x2 %0, %1, %2, %3;" : "=l"(d) : "l"(a), "l"(b), "l"(c)); return d;
}
__device__ __forceinline__ ull fmul2(ull a, ull b) {
    ull d; asm("mul.rn.f32x2 %0, %1, %2;" : "=l"(d) : "l"(a), "l"(b)); return d;
}
__device__ __forceinline__ ull fadd2(ull a, ull b) {
    ull d; asm("add.rn.f32x2 %0, %1, %2;" : "=l"(d) : "l"(a), "l"(b)); return d;
}
__device__ __forceinline__ ull pack2(float lo, float hi) {
    ull d; asm("mov.b64 %0, {%1, %2};" : "=l"(d) : "f"(lo), "f"(hi)); return d;
}
__device__ __forceinline__ void unpack2(ull v, float& lo, float& hi) {
    asm("mov.b64 {%0, %1}, %2;" : "=f"(lo), "=f"(hi) : "l"(v));
}
__device__ __forceinline__ float gelu_exact(float v) {
    return 0.5f * v * (1.0f + erff(v * 0.70710678118654752f));
}

// ---------------------------------------------------------------------------
// Prologue 1: transpose chk W1 [M][48][192] -> g_cw1t [M][192][52] (pad 48..51=0)
// ---------------------------------------------------------------------------
extern "C" __global__ void __launch_bounds__(128)
chk_w1t_prologue(const float* __restrict__ w1)
{
    __shared__ float sIn[CINC * 193];   // stride 193: conflict-free strided gather
    const int m = blockIdx.x, tid = threadIdx.x;
    const float* w1g = w1 + (size_t)m * CINC * HCC;
    for (int k = tid; k < CINC * HCC; k += 128) {
        int i = k / HCC, j = k - i * HCC;
        sIn[i * 193 + j] = w1g[k];
    }
    __syncthreads();
    float* outp = g_cw1t + (size_t)m * HCC * CINP;
    for (int k = tid; k < HCC * CINP; k += 128) {
        int j = k / CINP, i = k - j * CINP;
        outp[k] = (i < CINC) ? sIn[i * 193 + j] : 0.0f;
    }
}

// ---------------------------------------------------------------------------
// Prologue 2: var W1 [N][25][100] -> g_vw1t [N][100][28] (pad),
//             var W2 [N][100][25] -> g_vw2p [N][100][28] (pad)
// ---------------------------------------------------------------------------
extern "C" __global__ void __launch_bounds__(128)
var_wt_prologue(const float* __restrict__ w1, const float* __restrict__ w2)
{
    __shared__ float sIn[VINV * 101];
    const int n = blockIdx.x, tid = threadIdx.x;
    const float* w1g = w1 + (size_t)n * VINV * HVV;
    const float* w2g = w2 + (size_t)n * HVV * VINV;
    for (int k = tid; k < VINV * HVV; k += 128) {
        int i = k / HVV, j = k - i * HVV;
        sIn[i * 101 + j] = w1g[k];
    }
    __syncthreads();
    float* o1 = g_vw1t + (size_t)n * HVV * VINP;
    float* o2 = g_vw2p + (size_t)n * HVV * VINP;
    for (int k = tid; k < HVV * VINP; k += 128) {
        int j = k / VINP, i = k - j * VINP;
        o1[k] = (i < VINV) ? sIn[i * 101 + j] : 0.0f;
        o2[k] = (i < VINV) ? w2g[j * VINV + i] : 0.0f;
    }
}

// ---------------------------------------------------------------------------
// Check kernel: grid (MM, 2), 64 threads; thread handles batches tid, tid+64.
// Block (m, half) computes hidden [half*96, +96), writes PARTIAL y to g_cbuf[half].
// ---------------------------------------------------------------------------
extern "C" __global__ void __launch_bounds__(64, 4)
chk_kernel(const float* __restrict__ w2, const float* __restrict__ b1,
           const float* __restrict__ b2,
           const int* __restrict__ synd, const float* __restrict__ prior,
           const int* __restrict__ chk_nbrs, const int* __restrict__ v2c,
           int first)
{
    __shared__ __align__(16) float sW1T[HCH * CINP];
    __shared__ __align__(16) float sW2[HCH * CINC];
    __shared__ float sB1[HCH];
    __shared__ float sB2[CINC];
    __shared__ int   sIdx[DCC];

    const int m = blockIdx.x, half = blockIdx.y, tid = threadIdx.x;
    const int b0 = tid, b1v = tid + 64;

    // Stage pre-transposed weights: straight 16B copies
    {
        const ulonglong2* src1 =
            (const ulonglong2*)(g_cw1t + ((size_t)m * HCC + half * HCH) * CINP);
        ulonglong2* dst1 = (ulonglong2*)sW1T;
        for (int k = tid; k < HCH * CINP / 4; k += 64) dst1[k] = src1[k];
        const ulonglong2* src2 =
            (const ulonglong2*)(w2 + (size_t)m * HCC * CINC + (size_t)half * HCH * CINC);
        ulonglong2* dst2 = (ulonglong2*)sW2;
        for (int k = tid; k < HCH * CINC / 4; k += 64) dst2[k] = src2[k];
    }
    for (int k = tid; k < HCH; k += 64) sB1[k] = b1[(size_t)m * HCC + half * HCH + k];
    if (tid < CINC) sB2[tid] = (half == 0) ? b2[(size_t)m * CINC + tid] : 0.0f;
    if (tid < DCC)  sIdx[tid] = first ? chk_nbrs[m * DCC + tid] : v2c[m * DCC + tid];
    __syncthreads();

    ull xu0[24], xu1[24];
    if (first) {
        #pragma unroll
        for (int q = 0; q < 24; ++q) { xu0[q] = 0ULL; xu1[q] = 0ULL; }
        #pragma unroll
        for (int s = 0; s < DCC; ++s) {
            ull p = pack2(prior[sIdx[s]], 0.0f);
            xu0[s * 4] = p; xu1[s * 4] = p;
        }
    } else {
        #pragma unroll
        for (int s = 0; s < DCC; ++s) {
            size_t base = (size_t)sIdx[s] * BB * DD;
            const ulonglong2* s0 = (const ulonglong2*)(g_vbuf + base + (size_t)b0 * DD);
            const ulonglong2* s1 = (const ulonglong2*)(g_vbuf + base + (size_t)b1v * DD);
            ulonglong2 a = s0[0], c = s0[1];
            xu0[s * 4 + 0] = a.x; xu0[s * 4 + 1] = a.y;
            xu0[s * 4 + 2] = c.x; xu0[s * 4 + 3] = c.y;
            ulonglong2 e = s1[0], f = s1[1];
            xu1[s * 4 + 0] = e.x; xu1[s * 4 + 1] = e.y;
            xu1[s * 4 + 2] = f.x; xu1[s * 4 + 3] = f.y;
        }
    }
    const float sg0 = 1.0f - 2.0f * (float)synd[(size_t)b0 * MM + m];
    const float sg1 = 1.0f - 2.0f * (float)synd[(size_t)b1v * MM + m];

    ull yu0[24], yu1[24];
    #pragma unroll
    for (int q = 0; q < 24; ++q) {
        ull b = pack2(sB2[2 * q], sB2[2 * q + 1]);
        yu0[q] = b; yu1[q] = b;
    }

    #pragma unroll 2
    for (int j = 0; j < HCH; ++j) {
        const ulonglong2* wr = (const ulonglong2*)(sW1T + j * CINP);
        ull bj = pack2(sB1[j], 0.0f);
        ull a00 = bj, a01 = 0ULL, a10 = bj, a11 = 0ULL;
        #pragma unroll
        for (int q = 0; q < 12; ++q) {
            ulonglong2 w = wr[q];
            a00 = ffma2(xu0[2 * q],     w.x, a00);
            a10 = ffma2(xu1[2 * q],     w.x, a10);
            a01 = ffma2(xu0[2 * q + 1], w.y, a01);
            a11 = ffma2(xu1[2 * q + 1], w.y, a11);
        }
        float p0, p1, p2, p3;
        unpack2(a00, p0, p1); unpack2(a01, p2, p3);
        float h0 = gelu_exact((p0 + p1) + (p2 + p3));
        unpack2(a10, p0, p1); unpack2(a11, p2, p3);
        float h1 = gelu_exact((p0 + p1) + (p2 + p3));
        ull hh0 = pack2(h0, h0), hh1 = pack2(h1, h1);
        const ulonglong2* w2r = (const ulonglong2*)(sW2 + j * CINC);
        #pragma unroll
        for (int q = 0; q < 12; ++q) {
            ulonglong2 w = w2r[q];
            yu0[2 * q]     = ffma2(hh0, w.x, yu0[2 * q]);
            yu1[2 * q]     = ffma2(hh1, w.x, yu1[2 * q]);
            yu0[2 * q + 1] = ffma2(hh0, w.y, yu0[2 * q + 1]);
            yu1[2 * q + 1] = ffma2(hh1, w.y, yu1[2 * q + 1]);
        }
    }

    const ull sgp0 = pack2(sg0, sg0), sgp1 = pack2(sg1, sg1);
    float* obuf = g_cbuf + (size_t)half * PARTSZ;
    #pragma unroll
    for (int s = 0; s < DCC; ++s) {
        size_t base = (size_t)(m * DCC + s) * BB * DD;
        ulonglong2* d0 = (ulonglong2*)(obuf + base + (size_t)b0 * DD);
        ulonglong2* d1 = (ulonglong2*)(obuf + base + (size_t)b1v * DD);
        ulonglong2 o;
        o.x = fmul2(yu0[s * 4 + 0], sgp0); o.y = fmul2(yu0[s * 4 + 1], sgp0);
        d0[0] = o;
        o.x = fmul2(yu0[s * 4 + 2], sgp0); o.y = fmul2(yu0[s * 4 + 3], sgp0);
        d0[1] = o;
        o.x = fmul2(yu1[s * 4 + 0], sgp1); o.y = fmul2(yu1[s * 4 + 1], sgp1);
        d1[0] = o;
        o.x = fmul2(yu1[s * 4 + 2], sgp1); o.y = fmul2(yu1[s * 4 + 3], sgp1);
        d1[1] = o;
    }
}

// ---------------------------------------------------------------------------
// Var kernel: one block per var n, 64 threads; thread handles batches tid, tid+64.
// ---------------------------------------------------------------------------
extern "C" __global__ void __launch_bounds__(64, 6)
var_kernel(const float* __restrict__ b1, const float* __restrict__ b2,
           const float* __restrict__ prior, const int* __restrict__ c2v,
           float* __restrict__ out_t)
{
    __shared__ __align__(16) float sW1T[HVV * VINP];
    __shared__ __align__(16) float sW2[HVV * VINP];
    __shared__ float sB1[HVV];
    __shared__ float sB2[VINP];
    __shared__ int   sIdx[DVV];

    const int n = blockIdx.x, tid = threadIdx.x;
    const int b0 = tid, b1v = tid + 64;

    {
        const ulonglong2* src1 = (const ulonglong2*)(g_vw1t + (size_t)n * HVV * VINP);
        const ulonglong2* src2 = (const ulonglong2*)(g_vw2p + (size_t)n * HVV * VINP);
        ulonglong2* dst1 = (ulonglong2*)sW1T;
        ulonglong2* dst2 = (ulonglong2*)sW2;
        for (int k = tid; k < HVV * VINP / 4; k += 64) { dst1[k] = src1[k]; dst2[k] = src2[k]; }
    }
    for (int k = tid; k < HVV; k += 64) sB1[k] = b1[(size_t)n * HVV + k];
    if (tid < VINP) sB2[tid] = (tid < VINV) ? b2[(size_t)n * VINV + tid] : 0.0f;
    if (tid < DVV)  sIdx[tid] = c2v[n * DVV + tid];
    __syncthreads();

    ull xu0[14], xu1[14];
    #pragma unroll
    for (int l = 0; l < DVV; ++l) {
        size_t base = (size_t)sIdx[l] * BB * DD;
        const ulonglong2* sA0 = (const ulonglong2*)(g_cbuf + base + (size_t)b0 * DD);
        const ulonglong2* sB0 = (const ulonglong2*)(g_cbuf + PARTSZ + base + (size_t)b0 * DD);
        ulonglong2 a0 = sA0[0], a1 = sA0[1], c0 = sB0[0], c1 = sB0[1];
        xu0[l * 4 + 0] = fadd2(a0.x, c0.x);
        xu0[l * 4 + 1] = fadd2(a0.y, c0.y);
        xu0[l * 4 + 2] = fadd2(a1.x, c1.x);
        xu0[l * 4 + 3] = fadd2(a1.y, c1.y);
        const ulonglong2* sA1 = (const ulonglong2*)(g_cbuf + base + (size_t)b1v * DD);
        const ulonglong2* sB1p = (const ulonglong2*)(g_cbuf + PARTSZ + base + (size_t)b1v * DD);
        ulonglong2 e0 = sA1[0], e1 = sA1[1], f0 = sB1p[0], f1 = sB1p[1];
        xu1[l * 4 + 0] = fadd2(e0.x, f0.x);
        xu1[l * 4 + 1] = fadd2(e0.y, f0.y);
        xu1[l * 4 + 2] = fadd2(e1.x, f1.x);
        xu1[l * 4 + 3] = fadd2(e1.y, f1.y);
    }
    {
        ull p = pack2(prior[n], 0.0f);
        xu0[12] = p; xu1[12] = p;
        xu0[13] = 0ULL; xu1[13] = 0ULL;
    }

    ull yu0[14], yu1[14];
    #pragma unroll
    for (int q = 0; q < 14; ++q) {
        ull b = pack2(sB2[2 * q], sB2[2 * q + 1]);
        yu0[q] = b; yu1[q] = b;
    }

    #pragma unroll 2
    for (int j = 0; j < HVV; ++j) {
        const ulonglong2* wr = (const ulonglong2*)(sW1T + j * VINP);
        ull bj = pack2(sB1[j], 0.0f);
        ull a00 = bj, a01 = 0ULL, a10 = bj, a11 = 0ULL;
        #pragma unroll
        for (int q = 0; q < 7; ++q) {
            ulonglong2 w = wr[q];
            a00 = ffma2(xu0[2 * q],     w.x, a00);
            a10 = ffma2(xu1[2 * q],     w.x, a10);
            a01 = ffma2(xu0[2 * q + 1], w.y, a01);
            a11 = ffma2(xu1[2 * q + 1], w.y, a11);
        }
        float p0, p1, p2, p3;
        unpack2(a00, p0, p1); unpack2(a01, p2, p3);
        float h0 = gelu_exact((p0 + p1) + (p2 + p3));
        unpack2(a10, p0, p1); unpack2(a11, p2, p3);
        float h1 = gelu_exact((p0 + p1) + (p2 + p3));
        ull hh0 = pack2(h0, h0), hh1 = pack2(h1, h1);
        const ulonglong2* w2r = (const ulonglong2*)(sW2 + j * VINP);
        #pragma unroll
        for (int q = 0; q < 7; ++q) {
            ulonglong2 w = w2r[q];
            yu0[2 * q]     = ffma2(hh0, w.x, yu0[2 * q]);
            yu1[2 * q]     = ffma2(hh1, w.x, yu1[2 * q]);
            yu0[2 * q + 1] = ffma2(hh0, w.y, yu0[2 * q + 1]);
            yu1[2 * q + 1] = ffma2(hh1, w.y, yu1[2 * q + 1]);
        }
    }

    #pragma unroll
    for (int l = 0; l < DVV; ++l) {
        size_t base = (size_t)(n * DVV + l) * BB * DD;
        ulonglong2* d0 = (ulonglong2*)(g_vbuf + base + (size_t)b0 * DD);
        ulonglong2* d1 = (ulonglong2*)(g_vbuf + base + (size_t)b1v * DD);
        ulonglong2 o;
        o.x = yu0[l * 4 + 0]; o.y = yu0[l * 4 + 1]; d0[0] = o;
        o.x = yu0[l * 4 + 2]; o.y = yu0[l * 4 + 3]; d0[1] = o;
        o.x = yu1[l * 4 + 0]; o.y = yu1[l * 4 + 1]; d1[0] = o;
        o.x = yu1[l * 4 + 2]; o.y = yu1[l * 4 + 3]; d1[1] = o;
    }
    float lo, hi;
    unpack2(yu0[12], lo, hi); out_t[(size_t)b0 * NN + n] = lo;
    unpack2(yu1[12], lo, hi); out_t[(size_t)b1v * NN + n] = lo;
}

// ---------------------------------------------------------------------------
extern "C" void kernel_launch(void* const* d_in, const int* in_sizes, int n_in,
                              void* d_out, int out_size)
{
    const int*   synd  = (const int*)  d_in[0];
    const float* prior = (const float*)d_in[1];
    const float* cw1   = (const float*)d_in[2];
    const float* cb1   = (const float*)d_in[3];
    const float* cw2   = (const float*)d_in[4];
    const float* cb2   = (const float*)d_in[5];
    const float* vw1   = (const float*)d_in[6];
    const float* vb1   = (const float*)d_in[7];
    const float* vw2   = (const float*)d_in[8];
    const float* vb2   = (const float*)d_in[9];
    const int* chk_nbrs = (const int*)d_in[10];
    const int* c2v      = (const int*)d_in[11];
    const int* v2c      = (const int*)d_in[12];
    float* out = (float*)d_out;

    chk_w1t_prologue<<<MM, 128>>>(cw1);
    var_wt_prologue<<<NN, 128>>>(vw1, vw2);

    dim3 chk_grid(MM, 2);
    for (int t = 0; t < TT; ++t) {
        chk_kernel<<<chk_grid, 64>>>(cw2, cb1, cb2, synd, prior,
                                     chk_nbrs, v2c, (t == 0) ? 1 : 0);
        var_kernel<<<NN, 64>>>(vb1, vb2, prior, c2v, out + (size_t)t * BB * NN);
    }
}

// round 4
// speedup vs baseline: 1.4597x; 1.4597x over previous
#include <cuda_runtime.h>

// Problem constants
#define MM   1024
#define NN   2048
#define DVV  3
#define DCC  6
#define DD   8
#define BB   128
#define TT   5
#define CINC 48        // DC*D
#define CINP 52        // padded W1T row stride (floats, 16B-mult)
#define VINV 25        // DV*D + 1
#define VINP 28        // padded var width
#define HCC  192
#define HCH  96        // chk hidden half
#define HVV  100

#define PARTSZ ((size_t)MM * DCC * BB * DD)

typedef unsigned long long ull;

// Message buffers (edge-major: [edge][batch][D])
__device__ float g_cbuf[2 * PARTSZ];                  // check->var partial halves
__device__ float g_vbuf[(size_t)NN * DVV * BB * DD];  // var->check

// Pre-transposed / padded weights (filled by prologue kernels each replay)
__device__ float g_cw1t[(size_t)MM * HCC * CINP];     // [M][H][CINP]
__device__ float g_vw1t[(size_t)NN * HVV * VINP];     // [N][H][VINP]
__device__ float g_vw2p[(size_t)NN * HVV * VINP];     // [N][H][VINP]

__device__ __forceinline__ ull ffma2(ull a, ull b, ull c) {
    ull d; asm("fma.rn.f32x2 %0, %1, %2, %3;" : "=l"(d) : "l"(a), "l"(b), "l"(c)); return d;
}
__device__ __forceinline__ ull fmul2(ull a, ull b) {
    ull d; asm("mul.rn.f32x2 %0, %1, %2;" : "=l"(d) : "l"(a), "l"(b)); return d;
}
__device__ __forceinline__ ull fadd2(ull a, ull b) {
    ull d; asm("add.rn.f32x2 %0, %1, %2;" : "=l"(d) : "l"(a), "l"(b)); return d;
}
__device__ __forceinline__ ull pack2(float lo, float hi) {
    ull d; asm("mov.b64 %0, {%1, %2};" : "=l"(d) : "f"(lo), "f"(hi)); return d;
}
__device__ __forceinline__ void unpack2(ull v, float& lo, float& hi) {
    asm("mov.b64 {%0, %1}, %2;" : "=f"(lo), "=f"(hi) : "l"(v));
}
__device__ __forceinline__ float gelu_exact(float v) {
    return 0.5f * v * (1.0f + erff(v * 0.70710678118654752f));
}

// ---------------------------------------------------------------------------
// Prologue 1: transpose chk W1 [M][48][192] -> g_cw1t [M][192][52] (pad 48..51=0)
// ---------------------------------------------------------------------------
extern "C" __global__ void __launch_bounds__(128)
chk_w1t_prologue(const float* __restrict__ w1)
{
    __shared__ float sIn[CINC * 193];   // stride 193: conflict-free strided gather
    const int m = blockIdx.x, tid = threadIdx.x;
    const float* w1g = w1 + (size_t)m * CINC * HCC;
    for (int k = tid; k < CINC * HCC; k += 128) {
        int i = k / HCC, j = k - i * HCC;
        sIn[i * 193 + j] = w1g[k];
    }
    __syncthreads();
    float* outp = g_cw1t + (size_t)m * HCC * CINP;
    for (int k = tid; k < HCC * CINP; k += 128) {
        int j = k / CINP, i = k - j * CINP;
        outp[k] = (i < CINC) ? sIn[i * 193 + j] : 0.0f;
    }
}

// ---------------------------------------------------------------------------
// Prologue 2: var W1 [N][25][100] -> g_vw1t [N][100][28] (pad),
//             var W2 [N][100][25] -> g_vw2p [N][100][28] (pad)
// ---------------------------------------------------------------------------
extern "C" __global__ void __launch_bounds__(128)
var_wt_prologue(const float* __restrict__ w1, const float* __restrict__ w2)
{
    __shared__ float sIn[VINV * 101];
    const int n = blockIdx.x, tid = threadIdx.x;
    const float* w1g = w1 + (size_t)n * VINV * HVV;
    const float* w2g = w2 + (size_t)n * HVV * VINV;
    for (int k = tid; k < VINV * HVV; k += 128) {
        int i = k / HVV, j = k - i * HVV;
        sIn[i * 101 + j] = w1g[k];
    }
    __syncthreads();
    float* o1 = g_vw1t + (size_t)n * HVV * VINP;
    float* o2 = g_vw2p + (size_t)n * HVV * VINP;
    for (int k = tid; k < HVV * VINP; k += 128) {
        int j = k / VINP, i = k - j * VINP;
        o1[k] = (i < VINV) ? sIn[i * 101 + j] : 0.0f;
        o2[k] = (i < VINV) ? w2g[j * VINV + i] : 0.0f;
    }
}

// ---------------------------------------------------------------------------
// Check kernel: grid (MM, 2), 64 threads; thread handles batches tid, tid+64.
// Block (m, half) computes hidden [half*96, +96), writes PARTIAL y to g_cbuf[half].
// ---------------------------------------------------------------------------
extern "C" __global__ void __launch_bounds__(64, 4)
chk_kernel(const float* __restrict__ w2, const float* __restrict__ b1,
           const float* __restrict__ b2,
           const int* __restrict__ synd, const float* __restrict__ prior,
           const int* __restrict__ chk_nbrs, const int* __restrict__ v2c,
           int first)
{
    __shared__ __align__(16) float sW1T[HCH * CINP];
    __shared__ __align__(16) float sW2[HCH * CINC];
    __shared__ float sB1[HCH];
    __shared__ float sB2[CINC];
    __shared__ int   sIdx[DCC];

    const int m = blockIdx.x, half = blockIdx.y, tid = threadIdx.x;
    const int b0 = tid, b1v = tid + 64;

    // Stage pre-transposed weights: straight 16B copies
    {
        const ulonglong2* src1 =
            (const ulonglong2*)(g_cw1t + ((size_t)m * HCC + half * HCH) * CINP);
        ulonglong2* dst1 = (ulonglong2*)sW1T;
        for (int k = tid; k < HCH * CINP / 4; k += 64) dst1[k] = src1[k];
        const ulonglong2* src2 =
            (const ulonglong2*)(w2 + (size_t)m * HCC * CINC + (size_t)half * HCH * CINC);
        ulonglong2* dst2 = (ulonglong2*)sW2;
        for (int k = tid; k < HCH * CINC / 4; k += 64) dst2[k] = src2[k];
    }
    for (int k = tid; k < HCH; k += 64) sB1[k] = b1[(size_t)m * HCC + half * HCH + k];
    if (tid < CINC) sB2[tid] = (half == 0) ? b2[(size_t)m * CINC + tid] : 0.0f;
    if (tid < DCC)  sIdx[tid] = first ? chk_nbrs[m * DCC + tid] : v2c[m * DCC + tid];
    __syncthreads();

    ull xu0[24], xu1[24];
    if (first) {
        #pragma unroll
        for (int q = 0; q < 24; ++q) { xu0[q] = 0ULL; xu1[q] = 0ULL; }
        #pragma unroll
        for (int s = 0; s < DCC; ++s) {
            ull p = pack2(prior[sIdx[s]], 0.0f);
            xu0[s * 4] = p; xu1[s * 4] = p;
        }
    } else {
        #pragma unroll
        for (int s = 0; s < DCC; ++s) {
            size_t base = (size_t)sIdx[s] * BB * DD;
            const ulonglong2* s0 = (const ulonglong2*)(g_vbuf + base + (size_t)b0 * DD);
            const ulonglong2* s1 = (const ulonglong2*)(g_vbuf + base + (size_t)b1v * DD);
            ulonglong2 a = s0[0], c = s0[1];
            xu0[s * 4 + 0] = a.x; xu0[s * 4 + 1] = a.y;
            xu0[s * 4 + 2] = c.x; xu0[s * 4 + 3] = c.y;
            ulonglong2 e = s1[0], f = s1[1];
            xu1[s * 4 + 0] = e.x; xu1[s * 4 + 1] = e.y;
            xu1[s * 4 + 2] = f.x; xu1[s * 4 + 3] = f.y;
        }
    }
    const float sg0 = 1.0f - 2.0f * (float)synd[(size_t)b0 * MM + m];
    const float sg1 = 1.0f - 2.0f * (float)synd[(size_t)b1v * MM + m];

    ull yu0[24], yu1[24];
    #pragma unroll
    for (int q = 0; q < 24; ++q) {
        ull b = pack2(sB2[2 * q], sB2[2 * q + 1]);
        yu0[q] = b; yu1[q] = b;
    }

    #pragma unroll 2
    for (int j = 0; j < HCH; ++j) {
        const ulonglong2* wr = (const ulonglong2*)(sW1T + j * CINP);
        ull bj = pack2(sB1[j], 0.0f);
        ull a00 = bj, a01 = 0ULL, a10 = bj, a11 = 0ULL;
        #pragma unroll
        for (int q = 0; q < 12; ++q) {
            ulonglong2 w = wr[q];
            a00 = ffma2(xu0[2 * q],     w.x, a00);
            a10 = ffma2(xu1[2 * q],     w.x, a10);
            a01 = ffma2(xu0[2 * q + 1], w.y, a01);
            a11 = ffma2(xu1[2 * q + 1], w.y, a11);
        }
        float p0, p1, p2, p3;
        unpack2(a00, p0, p1); unpack2(a01, p2, p3);
        float h0 = gelu_exact((p0 + p1) + (p2 + p3));
        unpack2(a10, p0, p1); unpack2(a11, p2, p3);
        float h1 = gelu_exact((p0 + p1) + (p2 + p3));
        ull hh0 = pack2(h0, h0), hh1 = pack2(h1, h1);
        const ulonglong2* w2r = (const ulonglong2*)(sW2 + j * CINC);
        #pragma unroll
        for (int q = 0; q < 12; ++q) {
            ulonglong2 w = w2r[q];
            yu0[2 * q]     = ffma2(hh0, w.x, yu0[2 * q]);
            yu1[2 * q]     = ffma2(hh1, w.x, yu1[2 * q]);
            yu0[2 * q + 1] = ffma2(hh0, w.y, yu0[2 * q + 1]);
            yu1[2 * q + 1] = ffma2(hh1, w.y, yu1[2 * q + 1]);
        }
    }

    const ull sgp0 = pack2(sg0, sg0), sgp1 = pack2(sg1, sg1);
    float* obuf = g_cbuf + (size_t)half * PARTSZ;
    #pragma unroll
    for (int s = 0; s < DCC; ++s) {
        size_t base = (size_t)(m * DCC + s) * BB * DD;
        ulonglong2* d0 = (ulonglong2*)(obuf + base + (size_t)b0 * DD);
        ulonglong2* d1 = (ulonglong2*)(obuf + base + (size_t)b1v * DD);
        ulonglong2 o;
        o.x = fmul2(yu0[s * 4 + 0], sgp0); o.y = fmul2(yu0[s * 4 + 1], sgp0);
        d0[0] = o;
        o.x = fmul2(yu0[s * 4 + 2], sgp0); o.y = fmul2(yu0[s * 4 + 3], sgp0);
        d0[1] = o;
        o.x = fmul2(yu1[s * 4 + 0], sgp1); o.y = fmul2(yu1[s * 4 + 1], sgp1);
        d1[0] = o;
        o.x = fmul2(yu1[s * 4 + 2], sgp1); o.y = fmul2(yu1[s * 4 + 3], sgp1);
        d1[1] = o;
    }
}

// ---------------------------------------------------------------------------
// Var kernel: one block per var n, 64 threads; thread handles batches tid, tid+64.
// ---------------------------------------------------------------------------
extern "C" __global__ void __launch_bounds__(64, 6)
var_kernel(const float* __restrict__ b1, const float* __restrict__ b2,
           const float* __restrict__ prior, const int* __restrict__ c2v,
           float* __restrict__ out_t)
{
    __shared__ __align__(16) float sW1T[HVV * VINP];
    __shared__ __align__(16) float sW2[HVV * VINP];
    __shared__ float sB1[HVV];
    __shared__ float sB2[VINP];
    __shared__ int   sIdx[DVV];

    const int n = blockIdx.x, tid = threadIdx.x;
    const int b0 = tid, b1v = tid + 64;

    {
        const ulonglong2* src1 = (const ulonglong2*)(g_vw1t + (size_t)n * HVV * VINP);
        const ulonglong2* src2 = (const ulonglong2*)(g_vw2p + (size_t)n * HVV * VINP);
        ulonglong2* dst1 = (ulonglong2*)sW1T;
        ulonglong2* dst2 = (ulonglong2*)sW2;
        for (int k = tid; k < HVV * VINP / 4; k += 64) { dst1[k] = src1[k]; dst2[k] = src2[k]; }
    }
    for (int k = tid; k < HVV; k += 64) sB1[k] = b1[(size_t)n * HVV + k];
    if (tid < VINP) sB2[tid] = (tid < VINV) ? b2[(size_t)n * VINV + tid] : 0.0f;
    if (tid < DVV)  sIdx[tid] = c2v[n * DVV + tid];
    __syncthreads();

    ull xu0[14], xu1[14];
    #pragma unroll
    for (int l = 0; l < DVV; ++l) {
        size_t base = (size_t)sIdx[l] * BB * DD;
        const ulonglong2* sA0 = (const ulonglong2*)(g_cbuf + base + (size_t)b0 * DD);
        const ulonglong2* sB0 = (const ulonglong2*)(g_cbuf + PARTSZ + base + (size_t)b0 * DD);
        ulonglong2 a0 = sA0[0], a1 = sA0[1], c0 = sB0[0], c1 = sB0[1];
        xu0[l * 4 + 0] = fadd2(a0.x, c0.x);
        xu0[l * 4 + 1] = fadd2(a0.y, c0.y);
        xu0[l * 4 + 2] = fadd2(a1.x, c1.x);
        xu0[l * 4 + 3] = fadd2(a1.y, c1.y);
        const ulonglong2* sA1 = (const ulonglong2*)(g_cbuf + base + (size_t)b1v * DD);
        const ulonglong2* sB1p = (const ulonglong2*)(g_cbuf + PARTSZ + base + (size_t)b1v * DD);
        ulonglong2 e0 = sA1[0], e1 = sA1[1], f0 = sB1p[0], f1 = sB1p[1];
        xu1[l * 4 + 0] = fadd2(e0.x, f0.x);
        xu1[l * 4 + 1] = fadd2(e0.y, f0.y);
        xu1[l * 4 + 2] = fadd2(e1.x, f1.x);
        xu1[l * 4 + 3] = fadd2(e1.y, f1.y);
    }
    {
        ull p = pack2(prior[n], 0.0f);
        xu0[12] = p; xu1[12] = p;
        xu0[13] = 0ULL; xu1[13] = 0ULL;
    }

    ull yu0[14], yu1[14];
    #pragma unroll
    for (int q = 0; q < 14; ++q) {
        ull b = pack2(sB2[2 * q], sB2[2 * q + 1]);
        yu0[q] = b; yu1[q] = b;
    }

    #pragma unroll 2
    for (int j = 0; j < HVV; ++j) {
        const ulonglong2* wr = (const ulonglong2*)(sW1T + j * VINP);
        ull bj = pack2(sB1[j], 0.0f);
        ull a00 = bj, a01 = 0ULL, a10 = bj, a11 = 0ULL;
        #pragma unroll
        for (int q = 0; q < 7; ++q) {
            ulonglong2 w = wr[q];
            a00 = ffma2(xu0[2 * q],     w.x, a00);
            a10 = ffma2(xu1[2 * q],     w.x, a10);
            a01 = ffma2(xu0[2 * q + 1], w.y, a01);
            a11 = ffma2(xu1[2 * q + 1], w.y, a11);
        }
        float p0, p1, p2, p3;
        unpack2(a00, p0, p1); unpack2(a01, p2, p3);
        float h0 = gelu_exact((p0 + p1) + (p2 + p3));
        unpack2(a10, p0, p1); unpack2(a11, p2, p3);
        float h1 = gelu_exact((p0 + p1) + (p2 + p3));
        ull hh0 = pack2(h0, h0), hh1 = pack2(h1, h1);
        const ulonglong2* w2r = (const ulonglong2*)(sW2 + j * VINP);
        #pragma unroll
        for (int q = 0; q < 7; ++q) {
            ulonglong2 w = w2r[q];
            yu0[2 * q]     = ffma2(hh0, w.x, yu0[2 * q]);
            yu1[2 * q]     = ffma2(hh1, w.x, yu1[2 * q]);
            yu0[2 * q + 1] = ffma2(hh0, w.y, yu0[2 * q + 1]);
            yu1[2 * q + 1] = ffma2(hh1, w.y, yu1[2 * q + 1]);
        }
    }

    #pragma unroll
    for (int l = 0; l < DVV; ++l) {
        size_t base = (size_t)(n * DVV + l) * BB * DD;
        ulonglong2* d0 = (ulonglong2*)(g_vbuf + base + (size_t)b0 * DD);
        ulonglong2* d1 = (ulonglong2*)(g_vbuf + base + (size_t)b1v * DD);
        ulonglong2 o;
        o.x = yu0[l * 4 + 0]; o.y = yu0[l * 4 + 1]; d0[0] = o;
        o.x = yu0[l * 4 + 2]; o.y = yu0[l * 4 + 3]; d0[1] = o;
        o.x = yu1[l * 4 + 0]; o.y = yu1[l * 4 + 1]; d1[0] = o;
        o.x = yu1[l * 4 + 2]; o.y = yu1[l * 4 + 3]; d1[1] = o;
    }
    float lo, hi;
    unpack2(yu0[12], lo, hi); out_t[(size_t)b0 * NN + n] = lo;
    unpack2(yu1[12], lo, hi); out_t[(size_t)b1v * NN + n] = lo;
}

// ---------------------------------------------------------------------------
extern "C" void kernel_launch(void* const* d_in, const int* in_sizes, int n_in,
                              void* d_out, int out_size)
{
    const int*   synd  = (const int*)  d_in[0];
    const float* prior = (const float*)d_in[1];
    const float* cw1   = (const float*)d_in[2];
    const float* cb1   = (const float*)d_in[3];
    const float* cw2   = (const float*)d_in[4];
    const float* cb2   = (const float*)d_in[5];
    const float* vw1   = (const float*)d_in[6];
    const float* vb1   = (const float*)d_in[7];
    const float* vw2   = (const float*)d_in[8];
    const float* vb2   = (const float*)d_in[9];
    const int* chk_nbrs = (const int*)d_in[10];
    const int* c2v      = (const int*)d_in[11];
    const int* v2c      = (const int*)d_in[12];
    float* out = (float*)d_out;

    chk_w1t_prologue<<<MM, 128>>>(cw1);
    var_wt_prologue<<<NN, 128>>>(vw1, vw2);

    dim3 chk_grid(MM, 2);
    for (int t = 0; t < TT; ++t) {
        chk_kernel<<<chk_grid, 64>>>(cw2, cb1, cb2, synd, prior,
                                     chk_nbrs, v2c, (t == 0) ? 1 : 0);
        var_kernel<<<NN, 64>>>(vb1, vb2, prior, c2v, out + (size_t)t * BB * NN);
    }
}

// round 5
// speedup vs baseline: 1.5424x; 1.0566x over previous
#include <cuda_runtime.h>

// Problem constants
#define MM   1024
#define NN   2048
#define DVV  3
#define DCC  6
#define DD   8
#define BB   128
#define TT   5
#define CINC 48        // DC*D
#define CINP 52        // padded W1T row stride (floats, 16B-mult)
#define VINV 25        // DV*D + 1
#define VINP 28        // padded var width
#define HCC  192
#define HCH  96        // chk hidden half
#define HVV  100

#define PARTSZ ((size_t)MM * DCC * BB * DD)

typedef unsigned long long ull;

// Message buffers (edge-major: [edge][batch][D])
__device__ float g_cbuf[2 * PARTSZ];                  // check->var partial halves
__device__ float g_vbuf[(size_t)NN * DVV * BB * DD];  // var->check

// Pre-transposed / padded weights (filled by prologue kernels each replay)
__device__ float g_cw1t[(size_t)MM * HCC * CINP];     // [M][H][CINP]
__device__ float g_vw1t[(size_t)NN * HVV * VINP];     // [N][H][VINP]
__device__ float g_vw2p[(size_t)NN * HVV * VINP];     // [N][H][VINP]

__device__ __forceinline__ ull ffma2(ull a, ull b, ull c) {
    ull d; asm("fma.rn.f32x2 %0, %1, %2, %3;" : "=l"(d) : "l"(a), "l"(b), "l"(c)); return d;
}
__device__ __forceinline__ ull fmul2(ull a, ull b) {
    ull d; asm("mul.rn.f32x2 %0, %1, %2;" : "=l"(d) : "l"(a), "l"(b)); return d;
}
__device__ __forceinline__ ull fadd2(ull a, ull b) {
    ull d; asm("add.rn.f32x2 %0, %1, %2;" : "=l"(d) : "l"(a), "l"(b)); return d;
}
__device__ __forceinline__ ull pack2(float lo, float hi) {
    ull d; asm("mov.b64 %0, {%1, %2};" : "=l"(d) : "f"(lo), "f"(hi)); return d;
}
__device__ __forceinline__ void unpack2(ull v, float& lo, float& hi) {
    asm("mov.b64 {%0, %1}, %2;" : "=f"(lo), "=f"(hi) : "l"(v));
}

// Branch-free exact-GELU via Abramowitz-Stegun 7.1.26 erf (max abs err ~1.5e-7):
// erf(|x|) = 1 - (a1 t + a2 t^2 + a3 t^3 + a4 t^4 + a5 t^5) e^{-x^2},
// t = 1/(1 + 0.3275911 |x|)
__device__ __forceinline__ float gelu_fast(float v) {
    float x  = v * 0.70710678118654752f;
    float ax = fabsf(x);
    float t  = __fdividef(1.0f, fmaf(0.3275911f, ax, 1.0f));
    float e  = __expf(-ax * ax);
    float p  = fmaf(1.061405429f, t, -1.453152027f);
    p = fmaf(p, t, 1.421413741f);
    p = fmaf(p, t, -0.284496736f);
    p = fmaf(p, t, 0.254829592f);
    p = p * t;
    float r = fmaf(-p, e, 1.0f);          // erf(|x|)
    r = copysignf(r, x);                   // erf(x)
    float hv = 0.5f * v;
    return fmaf(hv, r, hv);                // 0.5 v (1 + erf(x))
}

// ---------------------------------------------------------------------------
// Prologue 1: transpose chk W1 [M][48][192] -> g_cw1t [M][192][52] (pad 48..51=0)
// ---------------------------------------------------------------------------
extern "C" __global__ void __launch_bounds__(128)
chk_w1t_prologue(const float* __restrict__ w1)
{
    __shared__ float sIn[CINC * 193];
    const int m = blockIdx.x, tid = threadIdx.x;
    const float* w1g = w1 + (size_t)m * CINC * HCC;
    for (int k = tid; k < CINC * HCC; k += 128) {
        int i = k / HCC, j = k - i * HCC;
        sIn[i * 193 + j] = w1g[k];
    }
    __syncthreads();
    float* outp = g_cw1t + (size_t)m * HCC * CINP;
    for (int k = tid; k < HCC * CINP; k += 128) {
        int j = k / CINP, i = k - j * CINP;
        outp[k] = (i < CINC) ? sIn[i * 193 + j] : 0.0f;
    }
}

// ---------------------------------------------------------------------------
// Prologue 2: var W1 [N][25][100] -> g_vw1t [N][100][28] (pad),
//             var W2 [N][100][25] -> g_vw2p [N][100][28] (pad)
// ---------------------------------------------------------------------------
extern "C" __global__ void __launch_bounds__(128)
var_wt_prologue(const float* __restrict__ w1, const float* __restrict__ w2)
{
    __shared__ float sIn[VINV * 101];
    const int n = blockIdx.x, tid = threadIdx.x;
    const float* w1g = w1 + (size_t)n * VINV * HVV;
    const float* w2g = w2 + (size_t)n * HVV * VINV;
    for (int k = tid; k < VINV * HVV; k += 128) {
        int i = k / HVV, j = k - i * HVV;
        sIn[i * 101 + j] = w1g[k];
    }
    __syncthreads();
    float* o1 = g_vw1t + (size_t)n * HVV * VINP;
    float* o2 = g_vw2p + (size_t)n * HVV * VINP;
    for (int k = tid; k < HVV * VINP; k += 128) {
        int j = k / VINP, i = k - j * VINP;
        o1[k] = (i < VINV) ? sIn[i * 101 + j] : 0.0f;
        o2[k] = (i < VINV) ? w2g[j * VINV + i] : 0.0f;
    }
}

// ---------------------------------------------------------------------------
// Check kernel: grid (MM, 2), 64 threads; thread handles batches tid, tid+64.
// Block (m, half) computes hidden [half*96, +96), writes PARTIAL y to g_cbuf[half].
// ---------------------------------------------------------------------------
extern "C" __global__ void __launch_bounds__(64, 4)
chk_kernel(const float* __restrict__ w2, const float* __restrict__ b1,
           const float* __restrict__ b2,
           const int* __restrict__ synd, const float* __restrict__ prior,
           const int* __restrict__ chk_nbrs, const int* __restrict__ v2c,
           int first)
{
    __shared__ __align__(16) float sW1T[HCH * CINP];
    __shared__ __align__(16) float sW2[HCH * CINC];
    __shared__ float sB1[HCH];
    __shared__ float sB2[CINC];
    __shared__ int   sIdx[DCC];

    const int m = blockIdx.x, half = blockIdx.y, tid = threadIdx.x;
    const int b0 = tid, b1v = tid + 64;

    {
        const ulonglong2* src1 =
            (const ulonglong2*)(g_cw1t + ((size_t)m * HCC + half * HCH) * CINP);
        ulonglong2* dst1 = (ulonglong2*)sW1T;
        for (int k = tid; k < HCH * CINP / 4; k += 64) dst1[k] = src1[k];
        const ulonglong2* src2 =
            (const ulonglong2*)(w2 + (size_t)m * HCC * CINC + (size_t)half * HCH * CINC);
        ulonglong2* dst2 = (ulonglong2*)sW2;
        for (int k = tid; k < HCH * CINC / 4; k += 64) dst2[k] = src2[k];
    }
    for (int k = tid; k < HCH; k += 64) sB1[k] = b1[(size_t)m * HCC + half * HCH + k];
    if (tid < CINC) sB2[tid] = (half == 0) ? b2[(size_t)m * CINC + tid] : 0.0f;
    if (tid < DCC)  sIdx[tid] = first ? chk_nbrs[m * DCC + tid] : v2c[m * DCC + tid];
    __syncthreads();

    ull xu0[24], xu1[24];
    if (first) {
        #pragma unroll
        for (int q = 0; q < 24; ++q) { xu0[q] = 0ULL; xu1[q] = 0ULL; }
        #pragma unroll
        for (int s = 0; s < DCC; ++s) {
            ull p = pack2(prior[sIdx[s]], 0.0f);
            xu0[s * 4] = p; xu1[s * 4] = p;
        }
    } else {
        #pragma unroll
        for (int s = 0; s < DCC; ++s) {
            size_t base = (size_t)sIdx[s] * BB * DD;
            const ulonglong2* s0 = (const ulonglong2*)(g_vbuf + base + (size_t)b0 * DD);
            const ulonglong2* s1 = (const ulonglong2*)(g_vbuf + base + (size_t)b1v * DD);
            ulonglong2 a = s0[0], c = s0[1];
            xu0[s * 4 + 0] = a.x; xu0[s * 4 + 1] = a.y;
            xu0[s * 4 + 2] = c.x; xu0[s * 4 + 3] = c.y;
            ulonglong2 e = s1[0], f = s1[1];
            xu1[s * 4 + 0] = e.x; xu1[s * 4 + 1] = e.y;
            xu1[s * 4 + 2] = f.x; xu1[s * 4 + 3] = f.y;
        }
    }
    const float sg0 = 1.0f - 2.0f * (float)synd[(size_t)b0 * MM + m];
    const float sg1 = 1.0f - 2.0f * (float)synd[(size_t)b1v * MM + m];

    ull yu0[24], yu1[24];
    #pragma unroll
    for (int q = 0; q < 24; ++q) {
        ull b = pack2(sB2[2 * q], sB2[2 * q + 1]);
        yu0[q] = b; yu1[q] = b;
    }

    #pragma unroll 2
    for (int j = 0; j < HCH; ++j) {
        const ulonglong2* wr = (const ulonglong2*)(sW1T + j * CINP);
        ull bj = pack2(sB1[j], 0.0f);
        ull a00 = bj, a01 = 0ULL, a10 = bj, a11 = 0ULL;
        #pragma unroll
        for (int q = 0; q < 12; ++q) {
            ulonglong2 w = wr[q];
            a00 = ffma2(xu0[2 * q],     w.x, a00);
            a10 = ffma2(xu1[2 * q],     w.x, a10);
            a01 = ffma2(xu0[2 * q + 1], w.y, a01);
            a11 = ffma2(xu1[2 * q + 1], w.y, a11);
        }
        float z0, z1, t0, t1;
        unpack2(fadd2(a00, a01), z0, t0);
        unpack2(fadd2(a10, a11), z1, t1);
        float h0 = gelu_fast(z0 + t0);
        float h1 = gelu_fast(z1 + t1);
        ull hh0 = pack2(h0, h0), hh1 = pack2(h1, h1);
        const ulonglong2* w2r = (const ulonglong2*)(sW2 + j * CINC);
        #pragma unroll
        for (int q = 0; q < 12; ++q) {
            ulonglong2 w = w2r[q];
            yu0[2 * q]     = ffma2(hh0, w.x, yu0[2 * q]);
            yu1[2 * q]     = ffma2(hh1, w.x, yu1[2 * q]);
            yu0[2 * q + 1] = ffma2(hh0, w.y, yu0[2 * q + 1]);
            yu1[2 * q + 1] = ffma2(hh1, w.y, yu1[2 * q + 1]);
        }
    }

    const ull sgp0 = pack2(sg0, sg0), sgp1 = pack2(sg1, sg1);
    float* obuf = g_cbuf + (size_t)half * PARTSZ;
    #pragma unroll
    for (int s = 0; s < DCC; ++s) {
        size_t base = (size_t)(m * DCC + s) * BB * DD;
        ulonglong2* d0 = (ulonglong2*)(obuf + base + (size_t)b0 * DD);
        ulonglong2* d1 = (ulonglong2*)(obuf + base + (size_t)b1v * DD);
        ulonglong2 o;
        o.x = fmul2(yu0[s * 4 + 0], sgp0); o.y = fmul2(yu0[s * 4 + 1], sgp0);
        d0[0] = o;
        o.x = fmul2(yu0[s * 4 + 2], sgp0); o.y = fmul2(yu0[s * 4 + 3], sgp0);
        d0[1] = o;
        o.x = fmul2(yu1[s * 4 + 0], sgp1); o.y = fmul2(yu1[s * 4 + 1], sgp1);
        d1[0] = o;
        o.x = fmul2(yu1[s * 4 + 2], sgp1); o.y = fmul2(yu1[s * 4 + 3], sgp1);
        d1[1] = o;
    }
}

// ---------------------------------------------------------------------------
// Var kernel: one block per var n, 64 threads; thread handles batches tid, tid+64.
// ---------------------------------------------------------------------------
extern "C" __global__ void __launch_bounds__(64, 6)
var_kernel(const float* __restrict__ b1, const float* __restrict__ b2,
           const float* __restrict__ prior, const int* __restrict__ c2v,
           float* __restrict__ out_t)
{
    __shared__ __align__(16) float sW1T[HVV * VINP];
    __shared__ __align__(16) float sW2[HVV * VINP];
    __shared__ float sB1[HVV];
    __shared__ float sB2[VINP];
    __shared__ int   sIdx[DVV];

    const int n = blockIdx.x, tid = threadIdx.x;
    const int b0 = tid, b1v = tid + 64;

    {
        const ulonglong2* src1 = (const ulonglong2*)(g_vw1t + (size_t)n * HVV * VINP);
        const ulonglong2* src2 = (const ulonglong2*)(g_vw2p + (size_t)n * HVV * VINP);
        ulonglong2* dst1 = (ulonglong2*)sW1T;
        ulonglong2* dst2 = (ulonglong2*)sW2;
        for (int k = tid; k < HVV * VINP / 4; k += 64) { dst1[k] = src1[k]; dst2[k] = src2[k]; }
    }
    for (int k = tid; k < HVV; k += 64) sB1[k] = b1[(size_t)n * HVV + k];
    if (tid < VINP) sB2[tid] = (tid < VINV) ? b2[(size_t)n * VINV + tid] : 0.0f;
    if (tid < DVV)  sIdx[tid] = c2v[n * DVV + tid];
    __syncthreads();

    ull xu0[14], xu1[14];
    #pragma unroll
    for (int l = 0; l < DVV; ++l) {
        size_t base = (size_t)sIdx[l] * BB * DD;
        const ulonglong2* sA0 = (const ulonglong2*)(g_cbuf + base + (size_t)b0 * DD);
        const ulonglong2* sB0 = (const ulonglong2*)(g_cbuf + PARTSZ + base + (size_t)b0 * DD);
        ulonglong2 a0 = sA0[0], a1 = sA0[1], c0 = sB0[0], c1 = sB0[1];
        xu0[l * 4 + 0] = fadd2(a0.x, c0.x);
        xu0[l * 4 + 1] = fadd2(a0.y, c0.y);
        xu0[l * 4 + 2] = fadd2(a1.x, c1.x);
        xu0[l * 4 + 3] = fadd2(a1.y, c1.y);
        const ulonglong2* sA1 = (const ulonglong2*)(g_cbuf + base + (size_t)b1v * DD);
        const ulonglong2* sB1p = (const ulonglong2*)(g_cbuf + PARTSZ + base + (size_t)b1v * DD);
        ulonglong2 e0 = sA1[0], e1 = sA1[1], f0 = sB1p[0], f1 = sB1p[1];
        xu1[l * 4 + 0] = fadd2(e0.x, f0.x);
        xu1[l * 4 + 1] = fadd2(e0.y, f0.y);
        xu1[l * 4 + 2] = fadd2(e1.x, f1.x);
        xu1[l * 4 + 3] = fadd2(e1.y, f1.y);
    }
    {
        ull p = pack2(prior[n], 0.0f);
        xu0[12] = p; xu1[12] = p;
        xu0[13] = 0ULL; xu1[13] = 0ULL;
    }

    ull yu0[14], yu1[14];
    #pragma unroll
    for (int q = 0; q < 14; ++q) {
        ull b = pack2(sB2[2 * q], sB2[2 * q + 1]);
        yu0[q] = b; yu1[q] = b;
    }

    #pragma unroll 2
    for (int j = 0; j < HVV; ++j) {
        const ulonglong2* wr = (const ulonglong2*)(sW1T + j * VINP);
        ull bj = pack2(sB1[j], 0.0f);
        ull a00 = bj, a01 = 0ULL, a10 = bj, a11 = 0ULL;
        #pragma unroll
        for (int q = 0; q < 7; ++q) {
            ulonglong2 w = wr[q];
            a00 = ffma2(xu0[2 * q],     w.x, a00);
            a10 = ffma2(xu1[2 * q],     w.x, a10);
            a01 = ffma2(xu0[2 * q + 1], w.y, a01);
            a11 = ffma2(xu1[2 * q + 1], w.y, a11);
        }
        float z0, z1, t0, t1;
        unpack2(fadd2(a00, a01), z0, t0);
        unpack2(fadd2(a10, a11), z1, t1);
        float h0 = gelu_fast(z0 + t0);
        float h1 = gelu_fast(z1 + t1);
        ull hh0 = pack2(h0, h0), hh1 = pack2(h1, h1);
        const ulonglong2* w2r = (const ulonglong2*)(sW2 + j * VINP);
        #pragma unroll
        for (int q = 0; q < 7; ++q) {
            ulonglong2 w = w2r[q];
            yu0[2 * q]     = ffma2(hh0, w.x, yu0[2 * q]);
            yu1[2 * q]     = ffma2(hh1, w.x, yu1[2 * q]);
            yu0[2 * q + 1] = ffma2(hh0, w.y, yu0[2 * q + 1]);
            yu1[2 * q + 1] = ffma2(hh1, w.y, yu1[2 * q + 1]);
        }
    }

    #pragma unroll
    for (int l = 0; l < DVV; ++l) {
        size_t base = (size_t)(n * DVV + l) * BB * DD;
        ulonglong2* d0 = (ulonglong2*)(g_vbuf + base + (size_t)b0 * DD);
        ulonglong2* d1 = (ulonglong2*)(g_vbuf + base + (size_t)b1v * DD);
        ulonglong2 o;
        o.x = yu0[l * 4 + 0]; o.y = yu0[l * 4 + 1]; d0[0] = o;
        o.x = yu0[l * 4 + 2]; o.y = yu0[l * 4 + 3]; d0[1] = o;
        o.x = yu1[l * 4 + 0]; o.y = yu1[l * 4 + 1]; d1[0] = o;
        o.x = yu1[l * 4 + 2]; o.y = yu1[l * 4 + 3]; d1[1] = o;
    }
    float lo, hi;
    unpack2(yu0[12], lo, hi); out_t[(size_t)b0 * NN + n] = lo;
    unpack2(yu1[12], lo, hi); out_t[(size_t)b1v * NN + n] = lo;
}

// ---------------------------------------------------------------------------
extern "C" void kernel_launch(void* const* d_in, const int* in_sizes, int n_in,
                              void* d_out, int out_size)
{
    const int*   synd  = (const int*)  d_in[0];
    const float* prior = (const float*)d_in[1];
    const float* cw1   = (const float*)d_in[2];
    const float* cb1   = (const float*)d_in[3];
    const float* cw2   = (const float*)d_in[4];
    const float* cb2   = (const float*)d_in[5];
    const float* vw1   = (const float*)d_in[6];
    const float* vb1   = (const float*)d_in[7];
    const float* vw2   = (const float*)d_in[8];
    const float* vb2   = (const float*)d_in[9];
    const int* chk_nbrs = (const int*)d_in[10];
    const int* c2v      = (const int*)d_in[11];
    const int* v2c      = (const int*)d_in[12];
    float* out = (float*)d_out;

    chk_w1t_prologue<<<MM, 128>>>(cw1);
    var_wt_prologue<<<NN, 128>>>(vw1, vw2);

    dim3 chk_grid(MM, 2);
    for (int t = 0; t < TT; ++t) {
        chk_kernel<<<chk_grid, 64>>>(cw2, cb1, cb2, synd, prior,
                                     chk_nbrs, v2c, (t == 0) ? 1 : 0);
        var_kernel<<<NN, 64>>>(vb1, vb2, prior, c2v, out + (size_t)t * BB * NN);
    }
}